// round 16
// baseline (speedup 1.0000x reference)
#include <cuda_runtime.h>
#include <math.h>

#define BATCH      512       // fixed by the problem's setup_inputs
#define CHUNK_RES  8         // residues per chunk (24 points)
#define CHUNK_PTS  (CHUNK_RES * 3)
#define MAXK       256       // chunks per chain supported (2048 residues)

// Scratch, all L2-resident:
//   g_chunk  [k][b] : chunk-product frames, 3 x float4 each (6.3 MB)
//   g_sprefix[ss][b]: exclusive superchunk prefixes
//   g_tloc   [k][pt][b]: per-point chunk-local translations, float4 (50 MB)
__device__ float4 g_chunk  [MAXK * BATCH * 3];
__device__ float4 g_sprefix[32   * BATCH * 3];
__device__ float4 g_tloc   [MAXK * CHUNK_PTS * BATCH];

// Completion counters (self-resetting; replay-stable)
__device__ unsigned g_acount = 0;   // blocks finished phase A
__device__ unsigned g_scount = 0;   // scan blocks finished

struct Geom { float ux[3]; float kk[3]; float L[3]; };

struct Frame {
    float r00, r01, r02, r10, r11, r12, r20, r21, r22;
    float tx, ty, tz;
};

__device__ __forceinline__ void frame_identity(Frame& f) {
    f.r00 = 1.f; f.r01 = 0.f; f.r02 = 0.f;
    f.r10 = 0.f; f.r11 = 1.f; f.r12 = 0.f;
    f.r20 = 0.f; f.r21 = 0.f; f.r22 = 1.f;
    f.tx = 0.f; f.ty = 0.f; f.tz = 0.f;
}

// G(s,c) directly (first extend from identity):
// columns [u, v, n]: u=(ux,ck,sk), v=(-kk,cux,sux), n=(0,-s,c); t = L*u
__device__ __forceinline__ void set_G(Frame& f, float s, float c,
                                      float ux, float kk, float L) {
    float ck = c * kk, sk = s * kk;
    f.r00 = ux; f.r01 = -kk;    f.r02 = 0.f;
    f.r10 = ck; f.r11 = c * ux; f.r12 = -s;
    f.r20 = sk; f.r21 = s * ux; f.r22 = c;
    f.tx = L * ux; f.ty = L * ck; f.tz = L * sk;
}

// F = F ∘ G(s,c | geometry)
__device__ __forceinline__ void extend(Frame& f, float s, float c,
                                       float ux, float kk, float L) {
    float ck  = c * kk, sk  = s * kk;
    float cux = c * ux, sux = s * ux;
    float a00 = fmaf(f.r00, ux, fmaf(f.r01, ck, f.r02 * sk));
    float a10 = fmaf(f.r10, ux, fmaf(f.r11, ck, f.r12 * sk));
    float a20 = fmaf(f.r20, ux, fmaf(f.r21, ck, f.r22 * sk));
    float a01 = fmaf(f.r01, cux, fmaf(f.r02, sux, -f.r00 * kk));
    float a11 = fmaf(f.r11, cux, fmaf(f.r12, sux, -f.r10 * kk));
    float a21 = fmaf(f.r21, cux, fmaf(f.r22, sux, -f.r20 * kk));
    float a02 = fmaf(f.r02, c, -f.r01 * s);
    float a12 = fmaf(f.r12, c, -f.r11 * s);
    float a22 = fmaf(f.r22, c, -f.r21 * s);
    f.tx = fmaf(L, a00, f.tx);
    f.ty = fmaf(L, a10, f.ty);
    f.tz = fmaf(L, a20, f.tz);
    f.r00 = a00; f.r01 = a01; f.r02 = a02;
    f.r10 = a10; f.r11 = a11; f.r12 = a12;
    f.r20 = a20; f.r21 = a21; f.r22 = a22;
}

// f = f ∘ g
__device__ __forceinline__ void compose(Frame& f, const Frame& g) {
    float tx = fmaf(f.r00, g.tx, fmaf(f.r01, g.ty, fmaf(f.r02, g.tz, f.tx)));
    float ty = fmaf(f.r10, g.tx, fmaf(f.r11, g.ty, fmaf(f.r12, g.tz, f.ty)));
    float tz = fmaf(f.r20, g.tx, fmaf(f.r21, g.ty, fmaf(f.r22, g.tz, f.tz)));
    float a00 = fmaf(f.r00, g.r00, fmaf(f.r01, g.r10, f.r02 * g.r20));
    float a01 = fmaf(f.r00, g.r01, fmaf(f.r01, g.r11, f.r02 * g.r21));
    float a02 = fmaf(f.r00, g.r02, fmaf(f.r01, g.r12, f.r02 * g.r22));
    float a10 = fmaf(f.r10, g.r00, fmaf(f.r11, g.r10, f.r12 * g.r20));
    float a11 = fmaf(f.r10, g.r01, fmaf(f.r11, g.r11, f.r12 * g.r21));
    float a12 = fmaf(f.r10, g.r02, fmaf(f.r11, g.r12, f.r12 * g.r22));
    float a20 = fmaf(f.r20, g.r00, fmaf(f.r21, g.r10, f.r22 * g.r20));
    float a21 = fmaf(f.r20, g.r01, fmaf(f.r21, g.r11, f.r22 * g.r21));
    float a22 = fmaf(f.r20, g.r02, fmaf(f.r21, g.r12, f.r22 * g.r22));
    f.r00 = a00; f.r01 = a01; f.r02 = a02;
    f.r10 = a10; f.r11 = a11; f.r12 = a12;
    f.r20 = a20; f.r21 = a21; f.r22 = a22;
    f.tx = tx; f.ty = ty; f.tz = tz;
}

__device__ __forceinline__ void store_frame4(float4* base, const Frame& f) {
    base[0] = make_float4(f.r00, f.r01, f.r02, f.r10);
    base[1] = make_float4(f.r11, f.r12, f.r20, f.r21);
    base[2] = make_float4(f.r22, f.tx,  f.ty,  f.tz);
}

__device__ __forceinline__ void load_frame4(const float4* base, Frame& f) {
    float4 a = base[0], b = base[1], c = base[2];
    f.r00 = a.x; f.r01 = a.y; f.r02 = a.z; f.r10 = a.w;
    f.r11 = b.x; f.r12 = b.y; f.r20 = b.z; f.r21 = b.w;
    f.r22 = c.x; f.tx  = c.y; f.ty  = c.z; f.tz  = c.w;
}

__device__ __forceinline__ Frame shfl_up_frame(const Frame& f, int d) {
    Frame o;
    o.r00 = __shfl_up_sync(0xFFFFFFFF, f.r00, d);
    o.r01 = __shfl_up_sync(0xFFFFFFFF, f.r01, d);
    o.r02 = __shfl_up_sync(0xFFFFFFFF, f.r02, d);
    o.r10 = __shfl_up_sync(0xFFFFFFFF, f.r10, d);
    o.r11 = __shfl_up_sync(0xFFFFFFFF, f.r11, d);
    o.r12 = __shfl_up_sync(0xFFFFFFFF, f.r12, d);
    o.r20 = __shfl_up_sync(0xFFFFFFFF, f.r20, d);
    o.r21 = __shfl_up_sync(0xFFFFFFFF, f.r21, d);
    o.r22 = __shfl_up_sync(0xFFFFFFFF, f.r22, d);
    o.tx  = __shfl_up_sync(0xFFFFFFFF, f.tx,  d);
    o.ty  = __shfl_up_sync(0xFFFFFFFF, f.ty,  d);
    o.tz  = __shfl_up_sync(0xFFFFFFFF, f.tz,  d);
    return o;
}

// Per-chain geometry: point m = 3l+q of chain b uses flat element
// D[l*1536 + q*512 + b], geometry index (q*512 + b) % 3.
__device__ __forceinline__ void chain_geom(const Geom& gm, int b,
                                           float* uxs, float* kks, float* Ls) {
    int g0 = b % 3;
    int g1 = (b + 2) % 3;
    int g2 = (b + 1) % 3;
    uxs[0] = gm.ux[g0]; kks[0] = gm.kk[g0]; Ls[0] = gm.L[g0];
    uxs[1] = gm.ux[g1]; kks[1] = gm.kk[g1]; Ls[1] = gm.L[g1];
    uxs[2] = gm.ux[g2]; kks[2] = gm.kk[g2]; Ls[2] = gm.L[g2];
}

// Kernel AS: phase A (chunk products + per-point chunk-local translations);
// the first nScanBlocks blocks then wait for global phase-A completion and
// run the superchunk warp scan. Other blocks exit -> no deadlock possible.
__global__ __launch_bounds__(128)
void kAS(const float* __restrict__ dih, Geom gm, int K, int LRES,
         int SUPW, int NSUP, int nScanBlocks) {
    int idx = blockIdx.x * blockDim.x + threadIdx.x;
    int lane = threadIdx.x & 31, wid = threadIdx.x >> 5;

    // ---------------- Phase A ----------------
    if (idx < BATCH * K) {
        int b = idx & (BATCH - 1);
        int k = idx >> 9;
        float uxs[3], kks[3], Ls[3];
        chain_geom(gm, b, uxs, kks, Ls);

        Frame f;
        int l0 = k * CHUNK_RES;
        int l1 = min(LRES, l0 + CHUNK_RES);
        float4* tb = g_tloc + ((size_t)k * CHUNK_PTS) * BATCH + b;
        bool first = true;
        for (int l = l0; l < l1; l++) {
            const float* dp = dih + (size_t)l * (3 * BATCH) + b;
            float d0 = dp[0], d1 = dp[BATCH], d2 = dp[2 * BATCH];
            float s, c;
            __sincosf(d0, &s, &c);
            if (first) { set_G(f, s, c, uxs[0], kks[0], Ls[0]); first = false; }
            else       { extend(f, s, c, uxs[0], kks[0], Ls[0]); }
            tb[0]         = make_float4(f.tx, f.ty, f.tz, 0.f);
            __sincosf(d1, &s, &c); extend(f, s, c, uxs[1], kks[1], Ls[1]);
            tb[BATCH]     = make_float4(f.tx, f.ty, f.tz, 0.f);
            __sincosf(d2, &s, &c); extend(f, s, c, uxs[2], kks[2], Ls[2]);
            tb[2 * BATCH] = make_float4(f.tx, f.ty, f.tz, 0.f);
            tb += 3 * BATCH;
        }
        store_frame4(g_chunk + ((size_t)k * BATCH + b) * 3, f);
    }

    __threadfence();
    __syncthreads();
    if (threadIdx.x == 0) atomicAdd(&g_acount, 1);

    if (blockIdx.x >= (unsigned)nScanBlocks) return;   // non-scan blocks exit

    if (threadIdx.x == 0) {
        while (*((volatile unsigned*)&g_acount) < gridDim.x) __nanosleep(64);
    }
    __syncthreads();
    __threadfence();

    // ---------------- Scan: warp per chain ----------------
    int sb = blockIdx.x * 4 + wid;       // nScanBlocks*4 warps cover BATCH chains
    if (sb < BATCH) {
        Frame f; frame_identity(f);
        if (lane < NSUP) {
            int k0 = lane * SUPW;
            int k1 = min(K, k0 + SUPW);
            int kk = k0;
            bool first = true;
            while (kk < k1) {
                Frame a; load_frame4(g_chunk + ((size_t)kk * BATCH + sb) * 3, a);
                if (kk + 1 < k1) {
                    Frame c2; load_frame4(g_chunk + ((size_t)(kk + 1) * BATCH + sb) * 3, c2);
                    compose(a, c2);
                    kk += 2;
                } else kk += 1;
                if (first) { f = a; first = false; }
                else       { compose(f, a); }
            }
        }
        #pragma unroll
        for (int d = 1; d < 32; d <<= 1) {
            Frame left = shfl_up_frame(f, d);
            Frame t = left;
            compose(t, f);
            if (lane >= d) f = t;
        }
        Frame ex = shfl_up_frame(f, 1);
        if (lane == 0) frame_identity(ex);
        if (lane < NSUP)
            store_frame4(g_sprefix + ((size_t)lane * BATCH + sb) * 3, ex);
    }

    // Last scan block resets counters for the next graph replay.
    __threadfence();
    __syncthreads();
    if (threadIdx.x == 0) {
        unsigned done = atomicAdd(&g_scount, 1);
        if (done == (unsigned)nScanBlocks - 1) {
            g_acount = 0;
            g_scount = 0;
            __threadfence();
        }
    }
}

// Kernel C: assemble chunk prefix (superchunk prefix + pairwise fixup), then
// per point: coord = R_pref * t_loc + t_pref — 9 FMA, no sincos, no extends,
// all points independent (pure ILP). Emit via double-buffered smem staging
// and float4 coalesced writeback.
__global__ __launch_bounds__(128)
void kC(float* __restrict__ out, int K, int LRES, int SUPW) {
    __shared__ __align__(16) float s_out[2][4][3 * 96]; // [buf][warp][q][96]
    int idx = blockIdx.x * blockDim.x + threadIdx.x;
    if (idx >= BATCH * K) return;
    int b = idx & (BATCH - 1);
    int k = idx >> 9;
    int ss = k / SUPW;
    int k0 = ss * SUPW;
    int lane = threadIdx.x & 31, wid = threadIdx.x >> 5;
    int b0 = b & ~31;

    // Prefix: pairwise fixup halves the dependent chain.
    Frame f;
    load_frame4(g_sprefix + ((size_t)ss * BATCH + b) * 3, f);
    {
        int kk = k0;
        while (kk + 1 < k) {
            Frame g1; load_frame4(g_chunk + ((size_t)kk       * BATCH + b) * 3, g1);
            Frame g2; load_frame4(g_chunk + ((size_t)(kk + 1) * BATCH + b) * 3, g2);
            compose(g1, g2);      // independent of f
            compose(f, g1);
            kk += 2;
        }
        if (kk < k) {
            Frame g; load_frame4(g_chunk + ((size_t)kk * BATCH + b) * 3, g);
            compose(f, g);
        }
    }

    int l0 = k * CHUNK_RES;
    int l1 = min(LRES, l0 + CHUNK_RES);
    const float4* __restrict__ tb = g_tloc + ((size_t)k * CHUNK_PTS) * BATCH + b;
    for (int l = l0; l < l1; l++) {
        float4 t0 = tb[0], t1 = tb[BATCH], t2 = tb[2 * BATCH];
        tb += 3 * BATCH;
        float* sw = s_out[l & 1][wid];

        // point 0
        sw[0 * 96 + lane * 3 + 0] = fmaf(f.r00, t0.x, fmaf(f.r01, t0.y, fmaf(f.r02, t0.z, f.tx)));
        sw[0 * 96 + lane * 3 + 1] = fmaf(f.r10, t0.x, fmaf(f.r11, t0.y, fmaf(f.r12, t0.z, f.ty)));
        sw[0 * 96 + lane * 3 + 2] = fmaf(f.r20, t0.x, fmaf(f.r21, t0.y, fmaf(f.r22, t0.z, f.tz)));
        // point 1
        sw[1 * 96 + lane * 3 + 0] = fmaf(f.r00, t1.x, fmaf(f.r01, t1.y, fmaf(f.r02, t1.z, f.tx)));
        sw[1 * 96 + lane * 3 + 1] = fmaf(f.r10, t1.x, fmaf(f.r11, t1.y, fmaf(f.r12, t1.z, f.ty)));
        sw[1 * 96 + lane * 3 + 2] = fmaf(f.r20, t1.x, fmaf(f.r21, t1.y, fmaf(f.r22, t1.z, f.tz)));
        // point 2
        sw[2 * 96 + lane * 3 + 0] = fmaf(f.r00, t2.x, fmaf(f.r01, t2.y, fmaf(f.r02, t2.z, f.tx)));
        sw[2 * 96 + lane * 3 + 1] = fmaf(f.r10, t2.x, fmaf(f.r11, t2.y, fmaf(f.r12, t2.z, f.ty)));
        sw[2 * 96 + lane * 3 + 2] = fmaf(f.r20, t2.x, fmaf(f.r21, t2.y, fmaf(f.r22, t2.z, f.tz)));
        __syncwarp();
        // Next iteration writes the OTHER buffer; reads below are protected
        // by the following iteration's syncwarp.

        float* obase = out + ((size_t)(3 * l) * BATCH + b0) * 3;
        if (lane < 24) {
            #pragma unroll
            for (int q = 0; q < 3; q++) {
                float4 v = reinterpret_cast<const float4*>(sw + q * 96)[lane];
                reinterpret_cast<float4*>(obase + (size_t)q * BATCH * 3)[lane] = v;
            }
        }
    }
}

extern "C" void kernel_launch(void* const* d_in, const int* in_sizes, int n_in,
                              void* d_out, int out_size) {
    const float* dih = (const float*)d_in[0];
    float* out = (float*)d_out;

    int Npts = in_sizes[0] / BATCH;
    int LRES = Npts / 3;
    int K = (LRES + CHUNK_RES - 1) / CHUNK_RES;
    if (K > MAXK) K = MAXK;
    int SUPW = (K + 31) / 32;
    int NSUP = (K + SUPW - 1) / SUPW;

    const double PI = 3.14159265358979323846;
    const float BL[3] = {145.801f, 152.326f, 132.868f};
    const float BA[3] = {2.124f, 1.941f, 2.028f};
    Geom gm;
    for (int d = 0; d < 3; d++) {
        double a  = PI - (double)BA[d];
        double rc = (double)BL[d] * cos(a);
        double rs = (double)BL[d] * sin(a);
        double L  = sqrt(rc * rc + rs * rs);
        gm.ux[d] = (float)(rc / L);
        gm.kk[d] = (float)(rs / L);
        gm.L[d]  = (float)L;
    }

    int nBlocks = (BATCH * K + 127) / 128;        // 1024 for this problem
    int nScanBlocks = (BATCH + 3) / 4;            // 128 blocks = 512 scan warps
    if (nScanBlocks > nBlocks) nScanBlocks = nBlocks;

    kAS<<<nBlocks, 128>>>(dih, gm, K, LRES, SUPW, NSUP, nScanBlocks);
    kC <<<nBlocks, 128>>>(out, K, LRES, SUPW);
}

// round 17
// speedup vs baseline: 1.3355x; 1.3355x over previous
#include <cuda_runtime.h>
#include <math.h>

#define BATCH      512       // fixed by the problem's setup_inputs
#define CHUNK_RES  8         // residues per chunk (24 points)
#define MAXK       512       // chunks per chain supported

// Scratch frames, layout [k][b][12 floats] as 3 x float4 per frame.
__device__ float4 g_chunk  [MAXK * BATCH * 3];
__device__ float4 g_sprefix[32   * BATCH * 3];

// Completion counters (self-resetting; replay-stable)
__device__ unsigned g_acount = 0;   // blocks finished phase A
__device__ unsigned g_scount = 0;   // scan blocks finished

struct Geom { float ux[3]; float kk[3]; float L[3]; };

struct Frame {
    float r00, r01, r02, r10, r11, r12, r20, r21, r22;
    float tx, ty, tz;
};

__device__ __forceinline__ void frame_identity(Frame& f) {
    f.r00 = 1.f; f.r01 = 0.f; f.r02 = 0.f;
    f.r10 = 0.f; f.r11 = 1.f; f.r12 = 0.f;
    f.r20 = 0.f; f.r21 = 0.f; f.r22 = 1.f;
    f.tx = 0.f; f.ty = 0.f; f.tz = 0.f;
}

// G(s,c) directly (first extend from identity):
// columns [u, v, n]: u=(ux,ck,sk), v=(-kk,cux,sux), n=(0,-s,c); t = L*u
__device__ __forceinline__ void set_G(Frame& f, float s, float c,
                                      float ux, float kk, float L) {
    float ck = c * kk, sk = s * kk;
    f.r00 = ux; f.r01 = -kk;    f.r02 = 0.f;
    f.r10 = ck; f.r11 = c * ux; f.r12 = -s;
    f.r20 = sk; f.r21 = s * ux; f.r22 = c;
    f.tx = L * ux; f.ty = L * ck; f.tz = L * sk;
}

// F = F ∘ G(s,c | geometry)
__device__ __forceinline__ void extend(Frame& f, float s, float c,
                                       float ux, float kk, float L) {
    float ck  = c * kk, sk  = s * kk;
    float cux = c * ux, sux = s * ux;
    float a00 = fmaf(f.r00, ux, fmaf(f.r01, ck, f.r02 * sk));
    float a10 = fmaf(f.r10, ux, fmaf(f.r11, ck, f.r12 * sk));
    float a20 = fmaf(f.r20, ux, fmaf(f.r21, ck, f.r22 * sk));
    float a01 = fmaf(f.r01, cux, fmaf(f.r02, sux, -f.r00 * kk));
    float a11 = fmaf(f.r11, cux, fmaf(f.r12, sux, -f.r10 * kk));
    float a21 = fmaf(f.r21, cux, fmaf(f.r22, sux, -f.r20 * kk));
    float a02 = fmaf(f.r02, c, -f.r01 * s);
    float a12 = fmaf(f.r12, c, -f.r11 * s);
    float a22 = fmaf(f.r22, c, -f.r21 * s);
    f.tx = fmaf(L, a00, f.tx);
    f.ty = fmaf(L, a10, f.ty);
    f.tz = fmaf(L, a20, f.tz);
    f.r00 = a00; f.r01 = a01; f.r02 = a02;
    f.r10 = a10; f.r11 = a11; f.r12 = a12;
    f.r20 = a20; f.r21 = a21; f.r22 = a22;
}

// f = f ∘ g
__device__ __forceinline__ void compose(Frame& f, const Frame& g) {
    float tx = fmaf(f.r00, g.tx, fmaf(f.r01, g.ty, fmaf(f.r02, g.tz, f.tx)));
    float ty = fmaf(f.r10, g.tx, fmaf(f.r11, g.ty, fmaf(f.r12, g.tz, f.ty)));
    float tz = fmaf(f.r20, g.tx, fmaf(f.r21, g.ty, fmaf(f.r22, g.tz, f.tz)));
    float a00 = fmaf(f.r00, g.r00, fmaf(f.r01, g.r10, f.r02 * g.r20));
    float a01 = fmaf(f.r00, g.r01, fmaf(f.r01, g.r11, f.r02 * g.r21));
    float a02 = fmaf(f.r00, g.r02, fmaf(f.r01, g.r12, f.r02 * g.r22));
    float a10 = fmaf(f.r10, g.r00, fmaf(f.r11, g.r10, f.r12 * g.r20));
    float a11 = fmaf(f.r10, g.r01, fmaf(f.r11, g.r11, f.r12 * g.r21));
    float a12 = fmaf(f.r10, g.r02, fmaf(f.r11, g.r12, f.r12 * g.r22));
    float a20 = fmaf(f.r20, g.r00, fmaf(f.r21, g.r10, f.r22 * g.r20));
    float a21 = fmaf(f.r20, g.r01, fmaf(f.r21, g.r11, f.r22 * g.r21));
    float a22 = fmaf(f.r20, g.r02, fmaf(f.r21, g.r12, f.r22 * g.r22));
    f.r00 = a00; f.r01 = a01; f.r02 = a02;
    f.r10 = a10; f.r11 = a11; f.r12 = a12;
    f.r20 = a20; f.r21 = a21; f.r22 = a22;
    f.tx = tx; f.ty = ty; f.tz = tz;
}

__device__ __forceinline__ void store_frame4(float4* base, const Frame& f) {
    base[0] = make_float4(f.r00, f.r01, f.r02, f.r10);
    base[1] = make_float4(f.r11, f.r12, f.r20, f.r21);
    base[2] = make_float4(f.r22, f.tx,  f.ty,  f.tz);
}

__device__ __forceinline__ void load_frame4(const float4* base, Frame& f) {
    float4 a = base[0], b = base[1], c = base[2];
    f.r00 = a.x; f.r01 = a.y; f.r02 = a.z; f.r10 = a.w;
    f.r11 = b.x; f.r12 = b.y; f.r20 = b.z; f.r21 = b.w;
    f.r22 = c.x; f.tx  = c.y; f.ty  = c.z; f.tz  = c.w;
}

__device__ __forceinline__ Frame shfl_up_frame(const Frame& f, int d) {
    Frame o;
    o.r00 = __shfl_up_sync(0xFFFFFFFF, f.r00, d);
    o.r01 = __shfl_up_sync(0xFFFFFFFF, f.r01, d);
    o.r02 = __shfl_up_sync(0xFFFFFFFF, f.r02, d);
    o.r10 = __shfl_up_sync(0xFFFFFFFF, f.r10, d);
    o.r11 = __shfl_up_sync(0xFFFFFFFF, f.r11, d);
    o.r12 = __shfl_up_sync(0xFFFFFFFF, f.r12, d);
    o.r20 = __shfl_up_sync(0xFFFFFFFF, f.r20, d);
    o.r21 = __shfl_up_sync(0xFFFFFFFF, f.r21, d);
    o.r22 = __shfl_up_sync(0xFFFFFFFF, f.r22, d);
    o.tx  = __shfl_up_sync(0xFFFFFFFF, f.tx,  d);
    o.ty  = __shfl_up_sync(0xFFFFFFFF, f.ty,  d);
    o.tz  = __shfl_up_sync(0xFFFFFFFF, f.tz,  d);
    return o;
}

// Per-chain geometry: point m = 3l+q of chain b uses flat element
// D[l*1536 + q*512 + b], geometry index (q*512 + b) % 3.
__device__ __forceinline__ void chain_geom(const Geom& gm, int b,
                                           float* uxs, float* kks, float* Ls) {
    int g0 = b % 3;
    int g1 = (b + 2) % 3;
    int g2 = (b + 1) % 3;
    uxs[0] = gm.ux[g0]; kks[0] = gm.kk[g0]; Ls[0] = gm.L[g0];
    uxs[1] = gm.ux[g1]; kks[1] = gm.kk[g1]; Ls[1] = gm.L[g1];
    uxs[2] = gm.ux[g2]; kks[2] = gm.kk[g2]; Ls[2] = gm.L[g2];
}

// Batch-load 4 residues' dihedrals (12 floats) starting at residue l.
__device__ __forceinline__ void load_dih4(const float* __restrict__ dih,
                                          int l, int b, float* d) {
    #pragma unroll
    for (int i = 0; i < 4; i++) {
        const float* dp = dih + (size_t)(l + i) * (3 * BATCH) + b;
        d[3 * i + 0] = dp[0];
        d[3 * i + 1] = dp[BATCH];
        d[3 * i + 2] = dp[2 * BATCH];
    }
}

// Kernel AS: phase A (chunk products) by all blocks; the first nScanBlocks
// blocks then wait for global phase-A completion and run the superchunk
// warp scan (one warp per chain). Other blocks exit -> no deadlock possible.
__global__ __launch_bounds__(128)
void kAS(const float* __restrict__ dih, Geom gm, int K, int LRES,
         int SUPW, int NSUP, int nScanBlocks) {
    int idx = blockIdx.x * blockDim.x + threadIdx.x;
    int lane = threadIdx.x & 31, wid = threadIdx.x >> 5;

    // ---------------- Phase A ----------------
    if (idx < BATCH * K) {
        int b = idx & (BATCH - 1);
        int k = idx >> 9;
        float uxs[3], kks[3], Ls[3];
        chain_geom(gm, b, uxs, kks, Ls);

        Frame f;
        int l0 = k * CHUNK_RES;
        int l1 = min(LRES, l0 + CHUNK_RES);
        float s, c;
        if (l1 - l0 == CHUNK_RES) {
            // Full chunk: batch loads (MLP 12) then compute.
            float d[12];
            load_dih4(dih, l0, b, d);
            __sincosf(d[0], &s, &c); set_G(f, s, c, uxs[0], kks[0], Ls[0]);
            __sincosf(d[1], &s, &c); extend(f, s, c, uxs[1], kks[1], Ls[1]);
            __sincosf(d[2], &s, &c); extend(f, s, c, uxs[2], kks[2], Ls[2]);
            #pragma unroll
            for (int i = 1; i < 4; i++) {
                __sincosf(d[3*i+0], &s, &c); extend(f, s, c, uxs[0], kks[0], Ls[0]);
                __sincosf(d[3*i+1], &s, &c); extend(f, s, c, uxs[1], kks[1], Ls[1]);
                __sincosf(d[3*i+2], &s, &c); extend(f, s, c, uxs[2], kks[2], Ls[2]);
            }
            load_dih4(dih, l0 + 4, b, d);
            #pragma unroll
            for (int i = 0; i < 4; i++) {
                __sincosf(d[3*i+0], &s, &c); extend(f, s, c, uxs[0], kks[0], Ls[0]);
                __sincosf(d[3*i+1], &s, &c); extend(f, s, c, uxs[1], kks[1], Ls[1]);
                __sincosf(d[3*i+2], &s, &c); extend(f, s, c, uxs[2], kks[2], Ls[2]);
            }
        } else {
            bool first = true;
            for (int l = l0; l < l1; l++) {
                const float* dp = dih + (size_t)l * (3 * BATCH) + b;
                float d0 = dp[0], d1 = dp[BATCH], d2 = dp[2 * BATCH];
                __sincosf(d0, &s, &c);
                if (first) { set_G(f, s, c, uxs[0], kks[0], Ls[0]); first = false; }
                else       { extend(f, s, c, uxs[0], kks[0], Ls[0]); }
                __sincosf(d1, &s, &c); extend(f, s, c, uxs[1], kks[1], Ls[1]);
                __sincosf(d2, &s, &c); extend(f, s, c, uxs[2], kks[2], Ls[2]);
            }
        }
        store_frame4(g_chunk + ((size_t)k * BATCH + b) * 3, f);
    }

    __threadfence();
    __syncthreads();
    if (threadIdx.x == 0) atomicAdd(&g_acount, 1);

    if (blockIdx.x >= (unsigned)nScanBlocks) return;   // non-scan blocks exit

    if (threadIdx.x == 0) {
        while (*((volatile unsigned*)&g_acount) < gridDim.x) __nanosleep(64);
    }
    __syncthreads();
    __threadfence();

    // ---------------- Scan: warp per chain ----------------
    int sb = blockIdx.x * 4 + wid;       // nScanBlocks*4 warps cover BATCH chains
    if (sb < BATCH) {
        Frame f; frame_identity(f);
        if (lane < NSUP) {
            int k0 = lane * SUPW;
            int k1 = min(K, k0 + SUPW);
            int kk = k0;
            bool first = true;
            while (kk < k1) {
                Frame a; load_frame4(g_chunk + ((size_t)kk * BATCH + sb) * 3, a);
                if (kk + 1 < k1) {
                    Frame c2; load_frame4(g_chunk + ((size_t)(kk + 1) * BATCH + sb) * 3, c2);
                    compose(a, c2);
                    kk += 2;
                } else kk += 1;
                if (first) { f = a; first = false; }
                else       { compose(f, a); }
            }
        }
        #pragma unroll
        for (int d = 1; d < 32; d <<= 1) {
            Frame left = shfl_up_frame(f, d);
            Frame t = left;
            compose(t, f);
            if (lane >= d) f = t;
        }
        Frame ex = shfl_up_frame(f, 1);
        if (lane == 0) frame_identity(ex);
        if (lane < NSUP)
            store_frame4(g_sprefix + ((size_t)lane * BATCH + sb) * 3, ex);
    }

    // Last scan block resets counters for the next graph replay.
    __threadfence();
    __syncthreads();
    if (threadIdx.x == 0) {
        unsigned done = atomicAdd(&g_scount, 1);
        if (done == (unsigned)nScanBlocks - 1) {
            g_acount = 0;
            g_scount = 0;
            __threadfence();
        }
    }
}

// One residue of kC: extend 3x, stage coords, writeback (float4 coalesced).
__device__ __forceinline__ void kc_residue(Frame& f, float d0, float d1, float d2,
                                           const float* uxs, const float* kks,
                                           const float* Ls, float* sw,
                                           float* __restrict__ out, int l,
                                           int b0, int lane) {
    float s, c;
    __sincosf(d0, &s, &c); extend(f, s, c, uxs[0], kks[0], Ls[0]);
    sw[0 * 96 + lane * 3 + 0] = f.tx;
    sw[0 * 96 + lane * 3 + 1] = f.ty;
    sw[0 * 96 + lane * 3 + 2] = f.tz;
    __sincosf(d1, &s, &c); extend(f, s, c, uxs[1], kks[1], Ls[1]);
    sw[1 * 96 + lane * 3 + 0] = f.tx;
    sw[1 * 96 + lane * 3 + 1] = f.ty;
    sw[1 * 96 + lane * 3 + 2] = f.tz;
    __sincosf(d2, &s, &c); extend(f, s, c, uxs[2], kks[2], Ls[2]);
    sw[2 * 96 + lane * 3 + 0] = f.tx;
    sw[2 * 96 + lane * 3 + 1] = f.ty;
    sw[2 * 96 + lane * 3 + 2] = f.tz;
    __syncwarp();
    // Next residue writes the OTHER smem buffer; the reads below are
    // protected by the following residue's syncwarp.
    float* obase = out + ((size_t)(3 * l) * BATCH + b0) * 3;
    if (lane < 24) {
        #pragma unroll
        for (int q = 0; q < 3; q++) {
            float4 v = reinterpret_cast<const float4*>(sw + q * 96)[lane];
            reinterpret_cast<float4*>(obase + (size_t)q * BATCH * 3)[lane] = v;
        }
    }
}

// Kernel C: pairwise fixup composes, replay the chunk with batched dihedral
// loads, emit via double-buffered smem staging + float4 writeback.
__global__ __launch_bounds__(128)
void kC(const float* __restrict__ dih, Geom gm, float* __restrict__ out,
        int K, int LRES, int SUPW) {
    __shared__ __align__(16) float s_out[2][4][3 * 96]; // [buf][warp][q][96]
    int idx = blockIdx.x * blockDim.x + threadIdx.x;
    if (idx >= BATCH * K) return;
    int b = idx & (BATCH - 1);
    int k = idx >> 9;
    int ss = k / SUPW;
    int k0 = ss * SUPW;
    int lane = threadIdx.x & 31, wid = threadIdx.x >> 5;
    int b0 = b & ~31;

    float uxs[3], kks[3], Ls[3];
    chain_geom(gm, b, uxs, kks, Ls);

    // Fixup: pairwise to halve the f-dependent chain (loads independent).
    Frame f;
    load_frame4(g_sprefix + ((size_t)ss * BATCH + b) * 3, f);
    {
        int kk = k0;
        while (kk + 1 < k) {
            Frame g1; load_frame4(g_chunk + ((size_t)kk       * BATCH + b) * 3, g1);
            Frame g2; load_frame4(g_chunk + ((size_t)(kk + 1) * BATCH + b) * 3, g2);
            compose(g1, g2);      // independent of f
            compose(f, g1);
            kk += 2;
        }
        if (kk < k) {
            Frame g; load_frame4(g_chunk + ((size_t)kk * BATCH + b) * 3, g);
            compose(f, g);
        }
    }

    int l0 = k * CHUNK_RES;
    int l1 = min(LRES, l0 + CHUNK_RES);
    if (l1 - l0 == CHUNK_RES) {
        float d[12];
        load_dih4(dih, l0, b, d);
        #pragma unroll
        for (int i = 0; i < 4; i++)
            kc_residue(f, d[3*i], d[3*i+1], d[3*i+2], uxs, kks, Ls,
                       s_out[i & 1][wid], out, l0 + i, b0, lane);
        load_dih4(dih, l0 + 4, b, d);
        #pragma unroll
        for (int i = 0; i < 4; i++)
            kc_residue(f, d[3*i], d[3*i+1], d[3*i+2], uxs, kks, Ls,
                       s_out[i & 1][wid], out, l0 + 4 + i, b0, lane);
    } else {
        for (int l = l0; l < l1; l++) {
            const float* dp = dih + (size_t)l * (3 * BATCH) + b;
            kc_residue(f, dp[0], dp[BATCH], dp[2 * BATCH], uxs, kks, Ls,
                       s_out[l & 1][wid], out, l, b0, lane);
        }
    }
}

extern "C" void kernel_launch(void* const* d_in, const int* in_sizes, int n_in,
                              void* d_out, int out_size) {
    const float* dih = (const float*)d_in[0];
    float* out = (float*)d_out;

    int Npts = in_sizes[0] / BATCH;
    int LRES = Npts / 3;
    int K = (LRES + CHUNK_RES - 1) / CHUNK_RES;
    if (K > MAXK) K = MAXK;
    int SUPW = (K + 31) / 32;
    int NSUP = (K + SUPW - 1) / SUPW;

    const double PI = 3.14159265358979323846;
    const float BL[3] = {145.801f, 152.326f, 132.868f};
    const float BA[3] = {2.124f, 1.941f, 2.028f};
    Geom gm;
    for (int d = 0; d < 3; d++) {
        double a  = PI - (double)BA[d];
        double rc = (double)BL[d] * cos(a);
        double rs = (double)BL[d] * sin(a);
        double L  = sqrt(rc * rc + rs * rs);
        gm.ux[d] = (float)(rc / L);
        gm.kk[d] = (float)(rs / L);
        gm.L[d]  = (float)L;
    }

    int nBlocks = (BATCH * K + 127) / 128;        // 1024 for this problem
    int nScanBlocks = (BATCH + 3) / 4;            // 128 blocks = 512 scan warps
    if (nScanBlocks > nBlocks) nScanBlocks = nBlocks;

    kAS<<<nBlocks, 128>>>(dih, gm, K, LRES, SUPW, NSUP, nScanBlocks);
    kC <<<nBlocks, 128>>>(dih, gm, out, K, LRES, SUPW);
}